// round 12
// baseline (speedup 1.0000x reference)
#include <cuda_runtime.h>
#include <cstdint>
#include <math.h>

#define NW 2048
#define TCC 12
#define TSS 4
#define HHd 128
#define Hd  256
#define Gd  512
#define WXD 768

typedef unsigned long long ull;

// ---------------- scratch (device globals; no allocation) ----------------
__device__ float g_X[TCC][NW][64];
__device__ float g_Xs[TSS][NW][64];
__device__ float g_P[2][TCC][NW][Gd];
__device__ float g_Ps[2][TSS][NW][Gd];
__device__ float g_h2[2][4][NW][HHd];
__device__ float g_c[4][NW][HHd];
__device__ float g_out[TCC][NW][Hd];
__device__ float g_outs[TSS][NW][Hd];
__device__ float g_E[TCC][NW][Hd];
__device__ float g_score[TCC][NW];
__device__ float g_wordx[NW][WXD];
__device__ float g_PW[2][NW][Gd];
__device__ float g_wout[NW][Hd];
__device__ float g_WhhP[4][Gd][HHd];
__device__ float g_WihP[4][Gd][64];
__device__ float g_bP[4][Gd];

// ---------------- fast math helpers ----------------
__device__ __forceinline__ float tanha(float x){
    float y; asm("tanh.approx.f32 %0, %1;" : "=f"(y) : "f"(x)); return y;
}
__device__ __forceinline__ float sigfast(float x){
    return fmaf(tanha(0.5f*x), 0.5f, 0.5f);
}
__device__ __forceinline__ ull ffma2(ull a, ull b, ull c){
    ull d;
    asm("fma.rn.f32x2 %0, %1, %2, %3;" : "=l"(d) : "l"(a), "l"(b), "l"(c));
    return d;
}
__device__ __forceinline__ ull pack2(float lo, float hi){
    ull d; asm("mov.b64 %0, {%1, %2};" : "=l"(d) : "f"(lo), "f"(hi)); return d;
}
__device__ __forceinline__ void unpack2(ull a, float& lo, float& hi){
    asm("mov.b64 {%0, %1}, %2;" : "=f"(lo), "=f"(hi) : "l"(a));
}
__device__ __forceinline__ float f2sum(ull a){
    float lo, hi; unpack2(a, lo, hi); return lo + hi;
}
__device__ __forceinline__ uint32_t bf16rn(float x){
    uint32_t u = __float_as_uint(x);
    return (u + 0x7fffu + ((u >> 16) & 1u)) >> 16;
}
__device__ __forceinline__ float blo(uint32_t p){ return __uint_as_float(p << 16); }
__device__ __forceinline__ float bhi(uint32_t p){ return __uint_as_float(p & 0xffff0000u); }

// ---------------- gather kernels ----------------
__global__ void k_gatherX(const int* __restrict__ ids, const float* __restrict__ emb,
                          float* __restrict__ dst, int T){
    int idx = blockIdx.x*256 + threadIdx.x;
    int total = NW*T*64;
    if (idx >= total) return;
    int dcol = idx & 63;
    int r = idx >> 6;
    int t = r % T, w = r / T;
    dst[((size_t)t*NW + w)*64 + dcol] = emb[(size_t)ids[r]*64 + dcol];
}

__global__ void k_init(const int* __restrict__ feat, const float* __restrict__ embp){
    int idx = blockIdx.x*256 + threadIdx.x;   // 4*NW*HH
    int q = idx >> 18;
    int d = q & 1;
    int w = (idx >> 7) & (NW-1);
    int j = idx & 127;
    g_h2[0][q][w][j] = embp[(size_t)feat[w]*Hd + d*HHd + j];
    g_c[q][w][j] = 0.f;
}

__global__ void k_gatherW(const int* __restrict__ wid, const float* __restrict__ embw){
    int idx = blockIdx.x*256 + threadIdx.x;
    int w = idx >> 8, j = idx & 255;
    g_wordx[w][j] = embw[(size_t)wid[w]*256 + j];
}

// gate-interleave permutation: slot (slot0+d), new row n = 4*j + g  <-  old row g*128 + j
__global__ void k_permW(const float* __restrict__ Wih, const float* __restrict__ Whh,
                        const float* __restrict__ bih, const float* __restrict__ bhh,
                        int slot0){
    int r = blockIdx.x*256 + threadIdx.x;
    if (r >= 1024) return;
    int d = r >> 9, n = r & 511;
    int g = n & 3, j = n >> 2;
    int oldr = g*128 + j;
    int slot = slot0 + d;
    const float4* sh_ = (const float4*)(Whh + ((size_t)d*Gd + oldr)*HHd);
    float4* dh = (float4*)&g_WhhP[slot][n][0];
    #pragma unroll
    for (int k=0;k<32;k++) dh[k] = sh_[k];
    const float4* si = (const float4*)(Wih + ((size_t)d*Gd + oldr)*64);
    float4* di = (float4*)&g_WihP[slot][n][0];
    #pragma unroll
    for (int k=0;k<16;k++) di[k] = si[k];
    g_bP[slot][n] = bih[d*Gd + oldr] + bhh[d*Gd + oldr];
}

// ---------------- GEMM: 128x64 block tile, 8x4 per-thread frag, z-batched ----------------
__global__ __launch_bounds__(256) void k_gemm(
    const float* __restrict__ A, const float* __restrict__ B,
    const float* __restrict__ bias0, const float* __restrict__ bias1,
    const float* __restrict__ C0, float* __restrict__ C,
    int M, int N, int K,
    long sB, long sBias, long sC0, long sC)
{
    __shared__ __align__(16) float As[2][16][136];
    __shared__ __align__(16) float Bs[2][16][72];
    long z = blockIdx.z;
    B += z*sB;
    if (bias0) bias0 += z*sBias;
    if (bias1) bias1 += z*sBias;
    if (C0) C0 += z*sC0;
    C += z*sC;
    int bn = blockIdx.x*64, bm = blockIdx.y*128;
    int tid = threadIdx.x;
    int tx = tid & 15, ty = tid >> 4;
    int ar = tid >> 1, ka = (tid & 1) << 3;
    int br = tid >> 2, kb = (tid & 3) << 2;

    const float* Ap = A + (size_t)(bm+ar)*K + ka;
    const float* Bp = B + (size_t)(bn+br)*K + kb;

    {
        float4 a0 = *(const float4*)Ap;
        float4 a1 = *(const float4*)(Ap+4);
        float4 b0 = *(const float4*)Bp;
        #pragma unroll
        for (int j=0;j<4;j++){
            As[0][ka+j][ar]   = (&a0.x)[j];
            As[0][ka+4+j][ar] = (&a1.x)[j];
            Bs[0][kb+j][br]   = (&b0.x)[j];
        }
    }
    __syncthreads();

    ull acc[8][2] = {};
    int buf = 0;
    for (int k0 = 16; ; k0 += 16){
        bool more = (k0 < K);
        float4 na0, na1, nb0;
        if (more){
            na0 = *(const float4*)(Ap + k0);
            na1 = *(const float4*)(Ap + k0 + 4);
            nb0 = *(const float4*)(Bp + k0);
        }
        #pragma unroll
        for (int k=0;k<16;k++){
            float4 av0 = *(const float4*)&As[buf][k][ty<<3];
            float4 av1 = *(const float4*)&As[buf][k][(ty<<3)+4];
            ulonglong2 bv = *(const ulonglong2*)&Bs[buf][k][tx<<2];
            float am[8] = { av0.x,av0.y,av0.z,av0.w, av1.x,av1.y,av1.z,av1.w };
            #pragma unroll
            for (int i=0;i<8;i++){
                ull ai = pack2(am[i], am[i]);
                acc[i][0] = ffma2(ai, bv.x, acc[i][0]);
                acc[i][1] = ffma2(ai, bv.y, acc[i][1]);
            }
        }
        if (!more) break;
        int nb = buf ^ 1;
        #pragma unroll
        for (int j=0;j<4;j++){
            As[nb][ka+j][ar]   = (&na0.x)[j];
            As[nb][ka+4+j][ar] = (&na1.x)[j];
            Bs[nb][kb+j][br]   = (&nb0.x)[j];
        }
        __syncthreads();
        buf = nb;
    }

    int n0 = bn + (tx<<2);
    float bb[4] = {0.f,0.f,0.f,0.f};
    if (bias0){ bb[0]=bias0[n0]; bb[1]=bias0[n0+1]; bb[2]=bias0[n0+2]; bb[3]=bias0[n0+3]; }
    if (bias1){ bb[0]+=bias1[n0]; bb[1]+=bias1[n0+1]; bb[2]+=bias1[n0+2]; bb[3]+=bias1[n0+3]; }
    #pragma unroll
    for (int i=0;i<8;i++){
        int m = bm + (ty<<3) + i;
        float4 v;
        unpack2(acc[i][0], v.x, v.y);
        unpack2(acc[i][1], v.z, v.w);
        v.x += bb[0]; v.y += bb[1]; v.z += bb[2]; v.w += bb[3];
        if (C0){
            float4 c0 = *(const float4*)&C0[(size_t)m*N + n0];
            v.x += c0.x; v.y += c0.y; v.z += c0.z; v.w += c0.w;
        }
        *(float4*)&C[(size_t)m*N + n0] = v;
    }
}

// ---------------- fused recurrence GEMM + LSTM pointwise, BOTH phases (z=4) ----------------
__global__ __launch_bounds__(256) void k_recfused(int s){
    int z = blockIdx.z;
    int p = z >> 1, d = z & 1;
    int T = p ? TSS : TCC;
    if (s >= T) return;
    __shared__ __align__(16) float As[2][16][136];
    __shared__ __align__(16) float Bs[2][16][72];
    int t = d ? (T-1-s) : s;
    int buf0 = s & 1;
    const float* A  = &g_h2[buf0][z][0][0];
    const float* B  = &g_WhhP[z][0][0];
    const float* C0 = p ? &g_Ps[d][t][0][0] : &g_P[d][t][0][0];
    float* cc   = &g_c[z][0][0];
    float* hnew = &g_h2[buf0^1][z][0][0];
    float* oout = p ? &g_outs[t][0][0] : &g_out[t][0][0];
    int bn = blockIdx.x*64, bm = blockIdx.y*128;
    int tid = threadIdx.x;
    int tx = tid & 15, ty = tid >> 4;
    int ar = tid >> 1, ka = (tid & 1) << 3;
    int br = tid >> 2, kb = (tid & 3) << 2;

    const float* Ap = A + (size_t)(bm+ar)*HHd + ka;
    const float* Bp = B + (size_t)(bn+br)*HHd + kb;

    {
        float4 a0 = *(const float4*)Ap;
        float4 a1 = *(const float4*)(Ap+4);
        float4 b0 = *(const float4*)Bp;
        #pragma unroll
        for (int j=0;j<4;j++){
            As[0][ka+j][ar]   = (&a0.x)[j];
            As[0][ka+4+j][ar] = (&a1.x)[j];
            Bs[0][kb+j][br]   = (&b0.x)[j];
        }
    }
    __syncthreads();

    ull acc[8][2] = {};
    int buf = 0;
    #pragma unroll 2
    for (int k0 = 16; ; k0 += 16){
        bool more = (k0 < HHd);
        float4 na0, na1, nb0;
        if (more){
            na0 = *(const float4*)(Ap + k0);
            na1 = *(const float4*)(Ap + k0 + 4);
            nb0 = *(const float4*)(Bp + k0);
        }
        #pragma unroll
        for (int k=0;k<16;k++){
            float4 av0 = *(const float4*)&As[buf][k][ty<<3];
            float4 av1 = *(const float4*)&As[buf][k][(ty<<3)+4];
            ulonglong2 bv = *(const ulonglong2*)&Bs[buf][k][tx<<2];
            float am[8] = { av0.x,av0.y,av0.z,av0.w, av1.x,av1.y,av1.z,av1.w };
            #pragma unroll
            for (int i=0;i<8;i++){
                ull ai = pack2(am[i], am[i]);
                acc[i][0] = ffma2(ai, bv.x, acc[i][0]);
                acc[i][1] = ffma2(ai, bv.y, acc[i][1]);
            }
        }
        if (!more) break;
        int nb = buf ^ 1;
        #pragma unroll
        for (int j=0;j<4;j++){
            As[nb][ka+j][ar]   = (&na0.x)[j];
            As[nb][ka+4+j][ar] = (&na1.x)[j];
            Bs[nb][kb+j][br]   = (&nb0.x)[j];
        }
        __syncthreads();
        buf = nb;
    }

    int n0 = bn + (tx<<2);
    int j = n0 >> 2;
    #pragma unroll
    for (int i=0;i<8;i++){
        int m = bm + (ty<<3) + i;
        float4 pg = *(const float4*)&C0[(size_t)m*Gd + n0];
        float gi,gf,gg,go;
        unpack2(acc[i][0], gi, gf);
        unpack2(acc[i][1], gg, go);
        gi += pg.x; gf += pg.y; gg += pg.z; go += pg.w;
        float c = sigfast(gf)*cc[(size_t)m*HHd + j] + sigfast(gi)*tanha(gg);
        float h = sigfast(go)*tanha(c);
        cc[(size_t)m*HHd + j] = c;
        hnew[(size_t)m*HHd + j] = h;
        oout[(size_t)m*Hd + d*HHd + j] = h;
    }
}

// ---------------- attention score ----------------
__global__ void k_score(int T, const float* __restrict__ wv){
    int gw = blockIdx.x*8 + (threadIdx.x >> 5);
    int lane = threadIdx.x & 31;
    if (gw >= T*NW) return;
    const float* e = &g_E[0][0][0] + (size_t)gw*Hd;
    float a = 0.f;
    #pragma unroll
    for (int i=0;i<8;i++){
        int g = lane + i*32;
        a += tanha(e[g]) * wv[g];
    }
    #pragma unroll
    for (int o=16;o;o>>=1) a += __shfl_xor_sync(0xffffffffu, a, o);
    if (lane == 0) (&g_score[0][0])[gw] = a;
}

// ---------------- softmax over t + weighted context ----------------
__global__ void k_softctx(int T, int off, const float* __restrict__ outp){
    int w = blockIdx.x, tid = threadIdx.x;
    __shared__ float sc[TCC];
    if (tid < T) sc[tid] = g_score[tid][w];
    __syncthreads();
    float m = -1e30f;
    for (int t=0;t<T;t++) m = fmaxf(m, sc[t]);
    float den = 0.f, acc = 0.f;
    for (int t=0;t<T;t++){
        float e = expf(sc[t]-m);
        den += e;
        acc += e * outp[((size_t)t*NW + w)*Hd + tid];
    }
    g_wordx[w][off + tid] = acc/den;
}

// ---------------- word-level sequential BiLSTM: 512 threads, 1 gate row each ----------
// 2 blocks (dir). Thread n owns gate row n (natural layout: i=0..127, f=128..255,
// g=256..383, o=384..511). Per row: 88 weights in regs (44 ull), 40 tail weights in
// smem as bf16 pairs: sW[n*20 + k] = { bf16(w[88+2k]), bf16(w[89+2k])<<16 }, k=0..19.
// stride 20 u32 = 5 16B-chunks, gcd(5,32)=1 -> conflict-free LDS.128.
// 16 warps (4/SMSP) for latency hiding. Pointwise on threads 0..127, c in register.
__global__ __launch_bounds__(512,1) void k_wordrec(
    const float* __restrict__ Whh, const float* __restrict__ PW, float* __restrict__ wout)
{
    __shared__ __align__(16) uint32_t sW[512*20];   // 40960 B
    __shared__ __align__(16) float sh[128];
    __shared__ __align__(16) float sg[512];
    int dir = blockIdx.x;
    int n   = threadIdx.x;                  // gate row
    const float* row = Whh + ((size_t)dir*Gd + n)*HHd;

    ull wa[44];
    {
        const ulonglong2* p0 = (const ulonglong2*)row;
        #pragma unroll
        for (int i=0;i<22;i++){
            ulonglong2 v0 = p0[i]; wa[2*i] = v0.x; wa[2*i+1] = v0.y;
        }
    }
    #pragma unroll
    for (int k=0;k<20;k++)
        sW[n*20 + k] = bf16rn(row[88+2*k]) | (bf16rn(row[89+2*k]) << 16);
    if (n < 128) sh[n] = 0.f;
    float c = 0.f;                          // cell state (valid on n<128)
    const float* PWd = PW + (size_t)dir*NW*Gd + n;
    __syncthreads();

    int tfirst = dir ? (NW-1) : 0;
    float pv = __ldg(PWd + (size_t)tfirst*Gd);

    for (int s=0;s<NW;s++){
        int t = dir ? (NW-1-s) : s;
        int sn = (s+1 < NW) ? s+1 : s;
        int tn = dir ? (NW-1-sn) : sn;
        float npv = __ldg(PWd + (size_t)tn*Gd);       // prefetch next step

        ull a0=0ull, a1=0ull;
        const ulonglong2* hp = (const ulonglong2*)sh;
        #pragma unroll
        for (int q=0;q<22;q++){
            ulonglong2 h2 = hp[q];            // h[4q..4q+3]
            a0 = ffma2(wa[2*q],   h2.x, a0);
            a1 = ffma2(wa[2*q+1], h2.y, a1);
        }
        #pragma unroll
        for (int u=0;u<5;u++){
            uint4 pw = *(const uint4*)&sW[n*20 + u*4];
            ulonglong2 h2a = hp[22 + 2*u];    // h[88+8u .. 91+8u]
            ulonglong2 h2b = hp[23 + 2*u];    // h[92+8u .. 95+8u]
            a0 = ffma2(pack2(blo(pw.x), bhi(pw.x)), h2a.x, a0);
            a1 = ffma2(pack2(blo(pw.y), bhi(pw.y)), h2a.y, a1);
            a0 = ffma2(pack2(blo(pw.z), bhi(pw.z)), h2b.x, a0);
            a1 = ffma2(pack2(blo(pw.w), bhi(pw.w)), h2b.y, a1);
        }
        sg[n] = pv + f2sum(a0) + f2sum(a1);
        pv = npv;
        __syncthreads();
        if (n < 128){
            float i_ = sg[n], f_ = sg[128+n], g_ = sg[256+n], o_ = sg[384+n];
            c = sigfast(f_)*c + sigfast(i_)*tanha(g_);
            float h = sigfast(o_)*tanha(c);
            sh[n] = h;
            wout[(size_t)t*Hd + dir*HHd + n] = h;
        }
        __syncthreads();
    }
}

// ---------------- final linear heads + log_softmax ----------------
__global__ void k_head(const float* __restrict__ wout,
                       const float* __restrict__ Wp, const float* __restrict__ bp,
                       const float* __restrict__ Wn, const float* __restrict__ bn_,
                       float* __restrict__ out)
{
    int w = blockIdx.x, tid = threadIdx.x;    // 64 threads
    __shared__ float h[Hd];
    __shared__ float lg[60];
    for (int i=tid;i<Hd;i+=64) h[i] = wout[w*Hd + i];
    __syncthreads();
    if (tid < 47){
        float a = bp[tid];
        const float* r = Wp + (size_t)tid*Hd;
        for (int k=0;k<Hd;k++) a += h[k]*r[k];
        lg[tid] = a;
    } else if (tid < 60){
        int n = tid-47;
        float a = bn_[n];
        const float* r = Wn + (size_t)n*Hd;
        for (int k=0;k<Hd;k++) a += h[k]*r[k];
        lg[tid] = a;
    }
    __syncthreads();
    if (tid < 47){
        float m = -1e30f;
        for (int i=0;i<47;i++) m = fmaxf(m, lg[i]);
        float s = 0.f;
        for (int i=0;i<47;i++) s += expf(lg[i]-m);
        out[(size_t)w*47 + tid] = lg[tid] - m - logf(s);
    } else if (tid < 60){
        float m = -1e30f;
        for (int i=47;i<60;i++) m = fmaxf(m, lg[i]);
        float s = 0.f;
        for (int i=47;i<60;i++) s += expf(lg[i]-m);
        out[(size_t)NW*47 + (size_t)w*13 + (tid-47)] = lg[tid] - m - logf(s);
    }
}

// ---------------- orchestration ----------------
extern "C" void kernel_launch(void* const* d_in, const int* in_sizes, int n_in,
                              void* d_out, int out_size)
{
    const int*   word_seq = (const int*)  d_in[0];
    const int*   syl_seq  = (const int*)  d_in[1];
    const int*   char_seq = (const int*)  d_in[2];
    const int*   feat_seq = (const int*)  d_in[3];
    const float* emb_char = (const float*)d_in[4];
    const float* emb_syl  = (const float*)d_in[5];
    const float* emb_word = (const float*)d_in[6];
    const float* emb_pref = (const float*)d_in[7];
    const float* aW_c = (const float*)d_in[8];
    const float* ab_c = (const float*)d_in[9];
    const float* aw_c = (const float*)d_in[10];
    const float* aW_s = (const float*)d_in[11];
    const float* ab_s = (const float*)d_in[12];
    const float* aw_s = (const float*)d_in[13];
    const float* cWih = (const float*)d_in[14];
    const float* cWhh = (const float*)d_in[15];
    const float* cbih = (const float*)d_in[16];
    const float* cbhh = (const float*)d_in[17];
    const float* sWih = (const float*)d_in[18];
    const float* sWhh = (const float*)d_in[19];
    const float* sbih = (const float*)d_in[20];
    const float* sbhh = (const float*)d_in[21];
    const float* wWih = (const float*)d_in[22];
    const float* wWhh = (const float*)d_in[23];
    const float* wbih = (const float*)d_in[24];
    const float* wbhh = (const float*)d_in[25];
    const float* Wp = (const float*)d_in[26];
    const float* bp = (const float*)d_in[27];
    const float* Wn = (const float*)d_in[28];
    const float* bn = (const float*)d_in[29];
    float* out = (float*)d_out;

    float *pX, *pXs, *pP, *pPs, *pE, *pWX, *pPW, *pWout, *pWihP, *pbP, *pOut, *pOuts;
    cudaGetSymbolAddress((void**)&pX,    g_X);
    cudaGetSymbolAddress((void**)&pXs,   g_Xs);
    cudaGetSymbolAddress((void**)&pP,    g_P);
    cudaGetSymbolAddress((void**)&pPs,   g_Ps);
    cudaGetSymbolAddress((void**)&pE,    g_E);
    cudaGetSymbolAddress((void**)&pWX,   g_wordx);
    cudaGetSymbolAddress((void**)&pPW,   g_PW);
    cudaGetSymbolAddress((void**)&pWout, g_wout);
    cudaGetSymbolAddress((void**)&pWihP, g_WihP);
    cudaGetSymbolAddress((void**)&pbP,   g_bP);
    cudaGetSymbolAddress((void**)&pOut,  g_out);
    cudaGetSymbolAddress((void**)&pOuts, g_outs);

    // ===== setup =====
    k_permW<<<4, 256>>>(cWih, cWhh, cbih, cbhh, 0);
    k_permW<<<4, 256>>>(sWih, sWhh, sbih, sbhh, 2);
    k_init<<<4096, 256>>>(feat_seq, emb_pref);
    k_gatherX<<<(NW*TCC*64 + 255)/256, 256>>>(char_seq, emb_char, pX, TCC);
    k_gatherX<<<(NW*TSS*64 + 255)/256, 256>>>(syl_seq, emb_syl, pXs, TSS);
    k_gatherW<<<NW, 256>>>(word_seq, emb_word);

    // ===== input projections =====
    k_gemm<<<dim3(Gd/64, (TCC*NW)/128, 2), 256>>>(
        pX, pWihP, pbP, nullptr, nullptr, pP,
        TCC*NW, Gd, 64,
        (long)Gd*64, (long)Gd, 0L, (long)TCC*NW*Gd);
    k_gemm<<<dim3(Gd/64, (TSS*NW)/128, 2), 256>>>(
        pXs, pWihP + (size_t)2*Gd*64, pbP + 2*Gd, nullptr, nullptr, pPs,
        TSS*NW, Gd, 64,
        (long)Gd*64, (long)Gd, 0L, (long)TSS*NW*Gd);

    // ===== recurrence: both phases + both directions per launch (z=4) =====
    for (int s = 0; s < TCC; s++)
        k_recfused<<<dim3(Gd/64, NW/128, 4), 256>>>(s);

    // ===== attention =====
    k_gemm<<<dim3(Hd/64, (TCC*NW)/128, 1), 256>>>(pOut, aW_c, ab_c, nullptr, nullptr, pE,
                                                  TCC*NW, Hd, Hd, 0L, 0L, 0L, 0L);
    k_score<<<(TCC*NW)/8, 256>>>(TCC, aw_c);
    k_softctx<<<NW, 256>>>(TCC, 256, pOut);

    k_gemm<<<dim3(Hd/64, (TSS*NW)/128, 1), 256>>>(pOuts, aW_s, ab_s, nullptr, nullptr, pE,
                                                  TSS*NW, Hd, Hd, 0L, 0L, 0L, 0L);
    k_score<<<(TSS*NW)/8, 256>>>(TSS, aw_s);
    k_softctx<<<NW, 256>>>(TSS, 512, pOuts);

    // ===== word-level BiLSTM =====
    k_gemm<<<dim3(Gd/64, NW/128, 2), 256>>>(
        pWX, wWih, wbih, wbhh, nullptr, pPW,
        NW, Gd, WXD,
        (long)Gd*WXD, (long)Gd, 0L, (long)NW*Gd);
    k_wordrec<<<2, 512>>>(wWhh, pPW, pWout);

    // ===== heads =====
    k_head<<<NW, 64>>>(pWout, Wp, bp, Wn, bn, out);
}

// round 14
// speedup vs baseline: 1.7615x; 1.7615x over previous
#include <cuda_runtime.h>
#include <cstdint>
#include <math.h>

#define NW 2048
#define TCC 12
#define TSS 4
#define HHd 128
#define Hd  256
#define Gd  512
#define WXD 768

typedef unsigned long long ull;

// ---------------- scratch (device globals; no allocation) ----------------
__device__ float g_X[TCC][NW][64];
__device__ float g_Xs[TSS][NW][64];
__device__ float g_P[2][TCC][NW][Gd];
__device__ float g_Ps[2][TSS][NW][Gd];
__device__ float g_h2[2][4][NW][HHd];
__device__ float g_c[4][NW][HHd];
__device__ float g_out[TCC][NW][Hd];
__device__ float g_outs[TSS][NW][Hd];
__device__ float g_score4[4][TCC*NW];     // per-N-tile partial attention scores (pitch TCC*NW)
__device__ float g_wordx[NW][WXD];
__device__ float g_PW[2][NW][Gd];
__device__ float g_wout[NW][Hd];
__device__ float g_WhhP[4][Gd][HHd];
__device__ float g_WihP[4][Gd][64];
__device__ float g_bP[4][Gd];

// ---------------- fast math helpers ----------------
__device__ __forceinline__ float tanha(float x){
    float y; asm("tanh.approx.f32 %0, %1;" : "=f"(y) : "f"(x)); return y;
}
__device__ __forceinline__ float sigfast(float x){
    return fmaf(tanha(0.5f*x), 0.5f, 0.5f);
}
__device__ __forceinline__ ull ffma2(ull a, ull b, ull c){
    ull d;
    asm("fma.rn.f32x2 %0, %1, %2, %3;" : "=l"(d) : "l"(a), "l"(b), "l"(c));
    return d;
}
__device__ __forceinline__ ull pack2(float lo, float hi){
    ull d; asm("mov.b64 %0, {%1, %2};" : "=l"(d) : "f"(lo), "f"(hi)); return d;
}
__device__ __forceinline__ void unpack2(ull a, float& lo, float& hi){
    asm("mov.b64 {%0, %1}, %2;" : "=f"(lo), "=f"(hi) : "l"(a));
}
__device__ __forceinline__ float f2sum(ull a){
    float lo, hi; unpack2(a, lo, hi); return lo + hi;
}
__device__ __forceinline__ uint32_t bf16rn(float x){
    uint32_t u = __float_as_uint(x);
    return (u + 0x7fffu + ((u >> 16) & 1u)) >> 16;
}
__device__ __forceinline__ float blo(uint32_t p){ return __uint_as_float(p << 16); }
__device__ __forceinline__ float bhi(uint32_t p){ return __uint_as_float(p & 0xffff0000u); }

// ---------------- gather kernels ----------------
__global__ void k_gatherX(const int* __restrict__ ids, const float* __restrict__ emb,
                          float* __restrict__ dst, int T){
    int idx = blockIdx.x*256 + threadIdx.x;
    int total = NW*T*64;
    if (idx >= total) return;
    int dcol = idx & 63;
    int r = idx >> 6;
    int t = r % T, w = r / T;
    dst[((size_t)t*NW + w)*64 + dcol] = emb[(size_t)ids[r]*64 + dcol];
}

__global__ void k_init(const int* __restrict__ feat, const float* __restrict__ embp){
    int idx = blockIdx.x*256 + threadIdx.x;   // 4*NW*HH
    int q = idx >> 18;
    int d = q & 1;
    int w = (idx >> 7) & (NW-1);
    int j = idx & 127;
    g_h2[0][q][w][j] = embp[(size_t)feat[w]*Hd + d*HHd + j];
    g_c[q][w][j] = 0.f;
}

__global__ void k_gatherW(const int* __restrict__ wid, const float* __restrict__ embw){
    int idx = blockIdx.x*256 + threadIdx.x;
    int w = idx >> 8, j = idx & 255;
    g_wordx[w][j] = embw[(size_t)wid[w]*256 + j];
}

// gate-interleave permutation: slot (slot0+d), new row n = 4*j + g  <-  old row g*128 + j
__global__ void k_permW(const float* __restrict__ Wih, const float* __restrict__ Whh,
                        const float* __restrict__ bih, const float* __restrict__ bhh,
                        int slot0){
    int r = blockIdx.x*256 + threadIdx.x;
    if (r >= 1024) return;
    int d = r >> 9, n = r & 511;
    int g = n & 3, j = n >> 2;
    int oldr = g*128 + j;
    int slot = slot0 + d;
    const float4* sh_ = (const float4*)(Whh + ((size_t)d*Gd + oldr)*HHd);
    float4* dh = (float4*)&g_WhhP[slot][n][0];
    #pragma unroll
    for (int k=0;k<32;k++) dh[k] = sh_[k];
    const float4* si = (const float4*)(Wih + ((size_t)d*Gd + oldr)*64);
    float4* di = (float4*)&g_WihP[slot][n][0];
    #pragma unroll
    for (int k=0;k<16;k++) di[k] = si[k];
    g_bP[slot][n] = bih[d*Gd + oldr] + bhh[d*Gd + oldr];
}

// ---------------- GEMM: 128x64 block tile, 8x4 per-thread frag, z-batched ----------------
__global__ __launch_bounds__(256) void k_gemm(
    const float* __restrict__ A, const float* __restrict__ B,
    const float* __restrict__ bias0, const float* __restrict__ bias1,
    const float* __restrict__ C0, float* __restrict__ C,
    int M, int N, int K,
    long sB, long sBias, long sC0, long sC)
{
    __shared__ __align__(16) float As[2][16][136];
    __shared__ __align__(16) float Bs[2][16][72];
    long z = blockIdx.z;
    B += z*sB;
    if (bias0) bias0 += z*sBias;
    if (bias1) bias1 += z*sBias;
    if (C0) C0 += z*sC0;
    C += z*sC;
    int bn = blockIdx.x*64, bm = blockIdx.y*128;
    int tid = threadIdx.x;
    int tx = tid & 15, ty = tid >> 4;
    int ar = tid >> 1, ka = (tid & 1) << 3;
    int br = tid >> 2, kb = (tid & 3) << 2;

    const float* Ap = A + (size_t)(bm+ar)*K + ka;
    const float* Bp = B + (size_t)(bn+br)*K + kb;

    {
        float4 a0 = *(const float4*)Ap;
        float4 a1 = *(const float4*)(Ap+4);
        float4 b0 = *(const float4*)Bp;
        #pragma unroll
        for (int j=0;j<4;j++){
            As[0][ka+j][ar]   = (&a0.x)[j];
            As[0][ka+4+j][ar] = (&a1.x)[j];
            Bs[0][kb+j][br]   = (&b0.x)[j];
        }
    }
    __syncthreads();

    ull acc[8][2] = {};
    int buf = 0;
    for (int k0 = 16; ; k0 += 16){
        bool more = (k0 < K);
        float4 na0, na1, nb0;
        if (more){
            na0 = *(const float4*)(Ap + k0);
            na1 = *(const float4*)(Ap + k0 + 4);
            nb0 = *(const float4*)(Bp + k0);
        }
        #pragma unroll
        for (int k=0;k<16;k++){
            float4 av0 = *(const float4*)&As[buf][k][ty<<3];
            float4 av1 = *(const float4*)&As[buf][k][(ty<<3)+4];
            ulonglong2 bv = *(const ulonglong2*)&Bs[buf][k][tx<<2];
            float am[8] = { av0.x,av0.y,av0.z,av0.w, av1.x,av1.y,av1.z,av1.w };
            #pragma unroll
            for (int i=0;i<8;i++){
                ull ai = pack2(am[i], am[i]);
                acc[i][0] = ffma2(ai, bv.x, acc[i][0]);
                acc[i][1] = ffma2(ai, bv.y, acc[i][1]);
            }
        }
        if (!more) break;
        int nb = buf ^ 1;
        #pragma unroll
        for (int j=0;j<4;j++){
            As[nb][ka+j][ar]   = (&na0.x)[j];
            As[nb][ka+4+j][ar] = (&na1.x)[j];
            Bs[nb][kb+j][br]   = (&nb0.x)[j];
        }
        __syncthreads();
        buf = nb;
    }

    int n0 = bn + (tx<<2);
    float bb[4] = {0.f,0.f,0.f,0.f};
    if (bias0){ bb[0]=bias0[n0]; bb[1]=bias0[n0+1]; bb[2]=bias0[n0+2]; bb[3]=bias0[n0+3]; }
    if (bias1){ bb[0]+=bias1[n0]; bb[1]+=bias1[n0+1]; bb[2]+=bias1[n0+2]; bb[3]+=bias1[n0+3]; }
    #pragma unroll
    for (int i=0;i<8;i++){
        int m = bm + (ty<<3) + i;
        float4 v;
        unpack2(acc[i][0], v.x, v.y);
        unpack2(acc[i][1], v.z, v.w);
        v.x += bb[0]; v.y += bb[1]; v.z += bb[2]; v.w += bb[3];
        if (C0){
            float4 c0 = *(const float4*)&C0[(size_t)m*N + n0];
            v.x += c0.x; v.y += c0.y; v.z += c0.z; v.w += c0.w;
        }
        *(float4*)&C[(size_t)m*N + n0] = v;
    }
}

// ---------------- attention GEMM + fused tanh·wv score reduction ----------------
// scorePart[bx*(TCC*NW) + m] = sum over this CTA's 64 columns of tanh(E[m][n]+bias)*wv[n].
// Partial pitch is the ALLOCATED row (TCC*NW), independent of the logical M.
__global__ __launch_bounds__(256) void k_gemmE(
    const float* __restrict__ A, const float* __restrict__ B,
    const float* __restrict__ bias0, const float* __restrict__ wv,
    float* __restrict__ scorePart,
    int M, int K)
{
    __shared__ __align__(16) float As[2][16][136];
    __shared__ __align__(16) float Bs[2][16][72];
    int bn = blockIdx.x*64, bm = blockIdx.y*128;
    int tid = threadIdx.x;
    int tx = tid & 15, ty = tid >> 4;
    int ar = tid >> 1, ka = (tid & 1) << 3;
    int br = tid >> 2, kb = (tid & 3) << 2;

    const float* Ap = A + (size_t)(bm+ar)*K + ka;
    const float* Bp = B + (size_t)(bn+br)*K + kb;

    {
        float4 a0 = *(const float4*)Ap;
        float4 a1 = *(const float4*)(Ap+4);
        float4 b0 = *(const float4*)Bp;
        #pragma unroll
        for (int j=0;j<4;j++){
            As[0][ka+j][ar]   = (&a0.x)[j];
            As[0][ka+4+j][ar] = (&a1.x)[j];
            Bs[0][kb+j][br]   = (&b0.x)[j];
        }
    }
    __syncthreads();

    ull acc[8][2] = {};
    int buf = 0;
    for (int k0 = 16; ; k0 += 16){
        bool more = (k0 < K);
        float4 na0, na1, nb0;
        if (more){
            na0 = *(const float4*)(Ap + k0);
            na1 = *(const float4*)(Ap + k0 + 4);
            nb0 = *(const float4*)(Bp + k0);
        }
        #pragma unroll
        for (int k=0;k<16;k++){
            float4 av0 = *(const float4*)&As[buf][k][ty<<3];
            float4 av1 = *(const float4*)&As[buf][k][(ty<<3)+4];
            ulonglong2 bv = *(const ulonglong2*)&Bs[buf][k][tx<<2];
            float am[8] = { av0.x,av0.y,av0.z,av0.w, av1.x,av1.y,av1.z,av1.w };
            #pragma unroll
            for (int i=0;i<8;i++){
                ull ai = pack2(am[i], am[i]);
                acc[i][0] = ffma2(ai, bv.x, acc[i][0]);
                acc[i][1] = ffma2(ai, bv.y, acc[i][1]);
            }
        }
        if (!more) break;
        int nb = buf ^ 1;
        #pragma unroll
        for (int j=0;j<4;j++){
            As[nb][ka+j][ar]   = (&na0.x)[j];
            As[nb][ka+4+j][ar] = (&na1.x)[j];
            Bs[nb][kb+j][br]   = (&nb0.x)[j];
        }
        __syncthreads();
        buf = nb;
    }

    int n0 = bn + (tx<<2);
    float4 bb = *(const float4*)&bias0[n0];
    float4 wv4 = *(const float4*)&wv[n0];
    #pragma unroll
    for (int i=0;i<8;i++){
        float4 v;
        unpack2(acc[i][0], v.x, v.y);
        unpack2(acc[i][1], v.z, v.w);
        float p = tanha(v.x+bb.x)*wv4.x + tanha(v.y+bb.y)*wv4.y
                + tanha(v.z+bb.z)*wv4.z + tanha(v.w+bb.w)*wv4.w;
        #pragma unroll
        for (int o=1;o<16;o<<=1) p += __shfl_xor_sync(0xffffffffu, p, o);
        if (tx == 0){
            int m = bm + (ty<<3) + i;
            scorePart[(size_t)blockIdx.x*(TCC*NW) + m] = p;   // FIX: pitch = TCC*NW always
        }
    }
}

// ---------------- fused recurrence GEMM + LSTM pointwise, BOTH phases (z=4) ----------------
__global__ __launch_bounds__(256) void k_recfused(int s){
    int z = blockIdx.z;
    int p = z >> 1, d = z & 1;
    int T = p ? TSS : TCC;
    if (s >= T) return;
    __shared__ __align__(16) float As[2][16][136];
    __shared__ __align__(16) float Bs[2][16][72];
    int t = d ? (T-1-s) : s;
    int buf0 = s & 1;
    const float* A  = &g_h2[buf0][z][0][0];
    const float* B  = &g_WhhP[z][0][0];
    const float* C0 = p ? &g_Ps[d][t][0][0] : &g_P[d][t][0][0];
    float* cc   = &g_c[z][0][0];
    float* hnew = &g_h2[buf0^1][z][0][0];
    float* oout = p ? &g_outs[t][0][0] : &g_out[t][0][0];
    int bn = blockIdx.x*64, bm = blockIdx.y*128;
    int tid = threadIdx.x;
    int tx = tid & 15, ty = tid >> 4;
    int ar = tid >> 1, ka = (tid & 1) << 3;
    int br = tid >> 2, kb = (tid & 3) << 2;

    const float* Ap = A + (size_t)(bm+ar)*HHd + ka;
    const float* Bp = B + (size_t)(bn+br)*HHd + kb;

    {
        float4 a0 = *(const float4*)Ap;
        float4 a1 = *(const float4*)(Ap+4);
        float4 b0 = *(const float4*)Bp;
        #pragma unroll
        for (int j=0;j<4;j++){
            As[0][ka+j][ar]   = (&a0.x)[j];
            As[0][ka+4+j][ar] = (&a1.x)[j];
            Bs[0][kb+j][br]   = (&b0.x)[j];
        }
    }
    __syncthreads();

    ull acc[8][2] = {};
    int buf = 0;
    #pragma unroll 2
    for (int k0 = 16; ; k0 += 16){
        bool more = (k0 < HHd);
        float4 na0, na1, nb0;
        if (more){
            na0 = *(const float4*)(Ap + k0);
            na1 = *(const float4*)(Ap + k0 + 4);
            nb0 = *(const float4*)(Bp + k0);
        }
        #pragma unroll
        for (int k=0;k<16;k++){
            float4 av0 = *(const float4*)&As[buf][k][ty<<3];
            float4 av1 = *(const float4*)&As[buf][k][(ty<<3)+4];
            ulonglong2 bv = *(const ulonglong2*)&Bs[buf][k][tx<<2];
            float am[8] = { av0.x,av0.y,av0.z,av0.w, av1.x,av1.y,av1.z,av1.w };
            #pragma unroll
            for (int i=0;i<8;i++){
                ull ai = pack2(am[i], am[i]);
                acc[i][0] = ffma2(ai, bv.x, acc[i][0]);
                acc[i][1] = ffma2(ai, bv.y, acc[i][1]);
            }
        }
        if (!more) break;
        int nb = buf ^ 1;
        #pragma unroll
        for (int j=0;j<4;j++){
            As[nb][ka+j][ar]   = (&na0.x)[j];
            As[nb][ka+4+j][ar] = (&na1.x)[j];
            Bs[nb][kb+j][br]   = (&nb0.x)[j];
        }
        __syncthreads();
        buf = nb;
    }

    int n0 = bn + (tx<<2);
    int j = n0 >> 2;
    #pragma unroll
    for (int i=0;i<8;i++){
        int m = bm + (ty<<3) + i;
        float4 pg = *(const float4*)&C0[(size_t)m*Gd + n0];
        float gi,gf,gg,go;
        unpack2(acc[i][0], gi, gf);
        unpack2(acc[i][1], gg, go);
        gi += pg.x; gf += pg.y; gg += pg.z; go += pg.w;
        float c = sigfast(gf)*cc[(size_t)m*HHd + j] + sigfast(gi)*tanha(gg);
        float h = sigfast(go)*tanha(c);
        cc[(size_t)m*HHd + j] = c;
        hnew[(size_t)m*HHd + j] = h;
        oout[(size_t)m*Hd + d*HHd + j] = h;
    }
}

// ---------------- softmax over t + weighted context (sums 4 score partials) ----------
__global__ void k_softctx(int T, int off, const float* __restrict__ outp){
    int w = blockIdx.x, tid = threadIdx.x;
    __shared__ float sc[TCC];
    if (tid < T){
        size_t m = (size_t)tid*NW + w;
        sc[tid] = g_score4[0][m] + g_score4[1][m] + g_score4[2][m] + g_score4[3][m];
    }
    __syncthreads();
    float mx = -1e30f;
    for (int t=0;t<T;t++) mx = fmaxf(mx, sc[t]);
    float den = 0.f, acc = 0.f;
    for (int t=0;t<T;t++){
        float e = expf(sc[t]-mx);
        den += e;
        acc += e * outp[((size_t)t*NW + w)*Hd + tid];
    }
    g_wordx[w][off + tid] = acc/den;
}

// ---------------- word-level sequential BiLSTM (R8: bf16 tail, 2 barriers) ----------
__global__ __launch_bounds__(256,1) void k_wordrec(
    const float* __restrict__ Whh, const float* __restrict__ PW, float* __restrict__ wout)
{
    __shared__ __align__(16) uint32_t sW[256*36];   // 36864 B
    __shared__ __align__(16) float sh[128];
    __shared__ __align__(16) float scc[128];
    __shared__ __align__(16) float sg[512];
    int dir = blockIdx.x;
    int t0  = threadIdx.x;
    int r0 = t0, r1 = t0 + 256;
    const float* row0 = Whh + ((size_t)dir*Gd + r0)*HHd;
    const float* row1 = Whh + ((size_t)dir*Gd + r1)*HHd;

    ull wa[48], wb[48];
    {
        const ulonglong2* p0 = (const ulonglong2*)row0;
        const ulonglong2* p1 = (const ulonglong2*)row1;
        #pragma unroll
        for (int i=0;i<24;i++){
            ulonglong2 v0 = p0[i]; wa[2*i] = v0.x; wa[2*i+1] = v0.y;
            ulonglong2 v1 = p1[i]; wb[2*i] = v1.x; wb[2*i+1] = v1.y;
        }
    }
    #pragma unroll
    for (int k=0;k<32;k++)
        sW[t0*36 + k] = bf16rn(row0[96+k]) | (bf16rn(row1[96+k]) << 16);
    if (t0 < 128){ sh[t0] = 0.f; scc[t0] = 0.f; }
    const float* PWd = PW + (size_t)dir*NW*Gd;
    __syncthreads();

    for (int s=0;s<NW;s++){
        int t = dir ? (NW-1-s) : s;
        float pv0 = __ldg(&PWd[(size_t)t*Gd + r0]);
        float pv1 = __ldg(&PWd[(size_t)t*Gd + r1]);
        ull a0=0ull, a1=0ull, a2=0ull, a3=0ull;
        const ulonglong2* hp = (const ulonglong2*)sh;
        #pragma unroll
        for (int q=0;q<24;q++){
            ulonglong2 h2 = hp[q];
            a0 = ffma2(wa[2*q],   h2.x, a0);
            a1 = ffma2(wa[2*q+1], h2.y, a1);
            a2 = ffma2(wb[2*q],   h2.x, a2);
            a3 = ffma2(wb[2*q+1], h2.y, a3);
        }
        #pragma unroll
        for (int q=0;q<8;q++){
            ulonglong2 h2 = hp[24+q];
            uint4 pw = *(const uint4*)&sW[t0*36 + q*4];
            ull W0a = pack2(blo(pw.x), blo(pw.y));
            ull W0b = pack2(blo(pw.z), blo(pw.w));
            ull W1a = pack2(bhi(pw.x), bhi(pw.y));
            ull W1b = pack2(bhi(pw.z), bhi(pw.w));
            a0 = ffma2(W0a, h2.x, a0);
            a1 = ffma2(W0b, h2.y, a1);
            a2 = ffma2(W1a, h2.x, a2);
            a3 = ffma2(W1b, h2.y, a3);
        }
        sg[r0] = pv0 + f2sum(a0) + f2sum(a1);
        sg[r1] = pv1 + f2sum(a2) + f2sum(a3);
        __syncthreads();
        if (t0 < 128){
            float i_ = sg[t0], f_ = sg[128+t0], g_ = sg[256+t0], o_ = sg[384+t0];
            float c = sigfast(f_)*scc[t0] + sigfast(i_)*tanha(g_);
            float h = sigfast(o_)*tanha(c);
            scc[t0] = c; sh[t0] = h;
            wout[(size_t)t*Hd + dir*HHd + t0] = h;
        }
        __syncthreads();
    }
}

// ---------------- final linear heads + log_softmax ----------------
__global__ void k_head(const float* __restrict__ wout,
                       const float* __restrict__ Wp, const float* __restrict__ bp,
                       const float* __restrict__ Wn, const float* __restrict__ bn_,
                       float* __restrict__ out)
{
    int w = blockIdx.x, tid = threadIdx.x;    // 64 threads
    __shared__ float h[Hd];
    __shared__ float lg[60];
    for (int i=tid;i<Hd;i+=64) h[i] = wout[w*Hd + i];
    __syncthreads();
    if (tid < 47){
        float a = bp[tid];
        const float* r = Wp + (size_t)tid*Hd;
        for (int k=0;k<Hd;k++) a += h[k]*r[k];
        lg[tid] = a;
    } else if (tid < 60){
        int n = tid-47;
        float a = bn_[n];
        const float* r = Wn + (size_t)n*Hd;
        for (int k=0;k<Hd;k++) a += h[k]*r[k];
        lg[tid] = a;
    }
    __syncthreads();
    if (tid < 47){
        float m = -1e30f;
        for (int i=0;i<47;i++) m = fmaxf(m, lg[i]);
        float s = 0.f;
        for (int i=0;i<47;i++) s += expf(lg[i]-m);
        out[(size_t)w*47 + tid] = lg[tid] - m - logf(s);
    } else if (tid < 60){
        float m = -1e30f;
        for (int i=47;i<60;i++) m = fmaxf(m, lg[i]);
        float s = 0.f;
        for (int i=47;i<60;i++) s += expf(lg[i]-m);
        out[(size_t)NW*47 + (size_t)w*13 + (tid-47)] = lg[tid] - m - logf(s);
    }
}

// ---------------- orchestration ----------------
extern "C" void kernel_launch(void* const* d_in, const int* in_sizes, int n_in,
                              void* d_out, int out_size)
{
    const int*   word_seq = (const int*)  d_in[0];
    const int*   syl_seq  = (const int*)  d_in[1];
    const int*   char_seq = (const int*)  d_in[2];
    const int*   feat_seq = (const int*)  d_in[3];
    const float* emb_char = (const float*)d_in[4];
    const float* emb_syl  = (const float*)d_in[5];
    const float* emb_word = (const float*)d_in[6];
    const float* emb_pref = (const float*)d_in[7];
    const float* aW_c = (const float*)d_in[8];
    const float* ab_c = (const float*)d_in[9];
    const float* aw_c = (const float*)d_in[10];
    const float* aW_s = (const float*)d_in[11];
    const float* ab_s = (const float*)d_in[12];
    const float* aw_s = (const float*)d_in[13];
    const float* cWih = (const float*)d_in[14];
    const float* cWhh = (const float*)d_in[15];
    const float* cbih = (const float*)d_in[16];
    const float* cbhh = (const float*)d_in[17];
    const float* sWih = (const float*)d_in[18];
    const float* sWhh = (const float*)d_in[19];
    const float* sbih = (const float*)d_in[20];
    const float* sbhh = (const float*)d_in[21];
    const float* wWih = (const float*)d_in[22];
    const float* wWhh = (const float*)d_in[23];
    const float* wbih = (const float*)d_in[24];
    const float* wbhh = (const float*)d_in[25];
    const float* Wp = (const float*)d_in[26];
    const float* bp = (const float*)d_in[27];
    const float* Wn = (const float*)d_in[28];
    const float* bn = (const float*)d_in[29];
    float* out = (float*)d_out;

    float *pX, *pXs, *pP, *pPs, *pWX, *pPW, *pWout, *pWihP, *pbP, *pOut, *pOuts, *pScore4;
    cudaGetSymbolAddress((void**)&pX,      g_X);
    cudaGetSymbolAddress((void**)&pXs,     g_Xs);
    cudaGetSymbolAddress((void**)&pP,      g_P);
    cudaGetSymbolAddress((void**)&pPs,     g_Ps);
    cudaGetSymbolAddress((void**)&pWX,     g_wordx);
    cudaGetSymbolAddress((void**)&pPW,     g_PW);
    cudaGetSymbolAddress((void**)&pWout,   g_wout);
    cudaGetSymbolAddress((void**)&pWihP,   g_WihP);
    cudaGetSymbolAddress((void**)&pbP,     g_bP);
    cudaGetSymbolAddress((void**)&pOut,    g_out);
    cudaGetSymbolAddress((void**)&pOuts,   g_outs);
    cudaGetSymbolAddress((void**)&pScore4, g_score4);

    // ===== setup =====
    k_permW<<<4, 256>>>(cWih, cWhh, cbih, cbhh, 0);
    k_permW<<<4, 256>>>(sWih, sWhh, sbih, sbhh, 2);
    k_init<<<4096, 256>>>(feat_seq, emb_pref);
    k_gatherX<<<(NW*TCC*64 + 255)/256, 256>>>(char_seq, emb_char, pX, TCC);
    k_gatherX<<<(NW*TSS*64 + 255)/256, 256>>>(syl_seq, emb_syl, pXs, TSS);
    k_gatherW<<<NW, 256>>>(word_seq, emb_word);

    // ===== input projections =====
    k_gemm<<<dim3(Gd/64, (TCC*NW)/128, 2), 256>>>(
        pX, pWihP, pbP, nullptr, nullptr, pP,
        TCC*NW, Gd, 64,
        (long)Gd*64, (long)Gd, 0L, (long)TCC*NW*Gd);
    k_gemm<<<dim3(Gd/64, (TSS*NW)/128, 2), 256>>>(
        pXs, pWihP + (size_t)2*Gd*64, pbP + 2*Gd, nullptr, nullptr, pPs,
        TSS*NW, Gd, 64,
        (long)Gd*64, (long)Gd, 0L, (long)TSS*NW*Gd);

    // ===== recurrence: both phases + both directions per launch (z=4) =====
    for (int s = 0; s < TCC; s++)
        k_recfused<<<dim3(Gd/64, NW/128, 4), 256>>>(s);

    // ===== attention: fused GEMM + tanh·wv reduction, then softmax-context =====
    k_gemmE<<<dim3(Hd/64, (TCC*NW)/128), 256>>>(pOut, aW_c, ab_c, aw_c, pScore4,
                                                TCC*NW, Hd);
    k_softctx<<<NW, 256>>>(TCC, 256, pOut);

    k_gemmE<<<dim3(Hd/64, (TSS*NW)/128), 256>>>(pOuts, aW_s, ab_s, aw_s, pScore4,
                                                TSS*NW, Hd);
    k_softctx<<<NW, 256>>>(TSS, 512, pOuts);

    // ===== word-level BiLSTM =====
    k_gemm<<<dim3(Gd/64, NW/128, 2), 256>>>(
        pWX, wWih, wbih, wbhh, nullptr, pPW,
        NW, Gd, WXD,
        (long)Gd*WXD, (long)Gd, 0L, (long)NW*Gd);
    k_wordrec<<<2, 256>>>(wWhh, pPW, pWout);

    // ===== heads =====
    k_head<<<NW, 64>>>(pWout, Wp, bp, Wn, bn, out);
}